// round 16
// baseline (speedup 1.0000x reference)
#include <cuda_runtime.h>
#include <cuda_bf16.h>
#include <cuda_fp16.h>
#include <cstdint>

#define BB 2
#define LL 2048
#define DD 1024
#define HH 16
#define HD 64
#define LD 256
#define BL (BB*LL)
#define NQ (HH*HD)

typedef __half hf;

__device__ float g_q[BL*NQ];
__device__ float g_oacc[BL*NQ];
__device__ float g_lacc[BL*HH];
__device__ hf g_xa_h[BL*DD], g_xa_l[BL*DD];
__device__ hf g_la_h[BL*LD], g_la_l[BL*LD];
__device__ hf g_ya[BL*NQ];
__device__ hf g_wq[NQ*DD];
__device__ hf g_wd_h[LD*DD], g_wd_l[LD*DD];
__device__ hf g_wk[NQ*LD];
__device__ hf g_wv_h[NQ*LD], g_wv_l[NQ*LD];
__device__ hf g_wo[DD*NQ];
__device__ hf g_kf[BB*HH*LL*HD];
__device__ hf g_vtf[BB*HH*HD*LL];

__device__ __forceinline__ void split2h(float x, float y, uint32_t& hi, uint32_t& lo) {
    __half2 h = __floats2half2_rn(x, y);
    float hx = __low2float(h), hy = __high2float(h);
    __half2 l = __floats2half2_rn(x - hx, y - hy);
    hi = *(uint32_t*)&h; lo = *(uint32_t*)&l;
}
__device__ __forceinline__ float ex2(float x) {
    float y; asm("ex2.approx.f32 %0, %1;" : "=f"(y) : "f"(x)); return y;
}
__device__ __forceinline__ void mmaf16(float* d, const uint32_t* a, uint32_t b0, uint32_t b1) {
    asm volatile("mma.sync.aligned.m16n8k16.row.col.f32.f16.f16.f32 "
        "{%0,%1,%2,%3}, {%4,%5,%6,%7}, {%8,%9}, {%0,%1,%2,%3};\n"
        : "+f"(d[0]), "+f"(d[1]), "+f"(d[2]), "+f"(d[3])
        : "r"(a[0]), "r"(a[1]), "r"(a[2]), "r"(a[3]), "r"(b0), "r"(b1));
}
__device__ __forceinline__ void ldsm4(uint32_t& r0, uint32_t& r1, uint32_t& r2, uint32_t& r3,
                                      const void* p) {
    uint32_t a = (uint32_t)__cvta_generic_to_shared(p);
    asm volatile("ldmatrix.sync.aligned.m8n8.x4.shared.b16 {%0,%1,%2,%3}, [%4];\n"
        : "=r"(r0), "=r"(r1), "=r"(r2), "=r"(r3) : "r"(a));
}
__device__ __forceinline__ void cpa16(void* dst, const void* src) {
    uint32_t a = (uint32_t)__cvta_generic_to_shared(dst);
    asm volatile("cp.async.cg.shared.global [%0], [%1], 16;\n" :: "r"(a), "l"(src));
}
__device__ __forceinline__ void cpa_commit() { asm volatile("cp.async.commit_group;\n"); }
__device__ __forceinline__ void cpa_wait0()  { asm volatile("cp.async.wait_group 0;\n"); }
__device__ __forceinline__ void cpa_wait1()  { asm volatile("cp.async.wait_group 1;\n"); }

// ---------------- fused conversions ----------------
__device__ __forceinline__ void conv_T_hl(
    const float* __restrict__ src, hf* __restrict__ dh, hf* __restrict__ dl,
    int R, int C, int cx, int rx)
{
    __shared__ float t[32][33];
    int x = threadIdx.x & 31, y8 = threadIdx.x >> 5;
    int c0 = cx * 32, r0 = rx * 32;
    #pragma unroll
    for (int it = 0; it < 4; it++)
        t[y8 + it * 8][x] = src[(size_t)(r0 + y8 + it * 8) * C + c0 + x];
    __syncthreads();
    #pragma unroll
    for (int it = 0; it < 4; it++) {
        int cc = y8 + it * 8;
        float v = t[x][cc];
        hf h = __float2half(v);
        dh[(size_t)(c0 + cc) * R + r0 + x] = h;
        dl[(size_t)(c0 + cc) * R + r0 + x] = __float2half(v - __half2float(h));
    }
}
__device__ __forceinline__ void conv_T_s(
    const float* __restrict__ src, hf* __restrict__ d,
    int R, int C, int cx, int rx)
{
    __shared__ float t[32][33];
    int x = threadIdx.x & 31, y8 = threadIdx.x >> 5;
    int c0 = cx * 32, r0 = rx * 32;
    #pragma unroll
    for (int it = 0; it < 4; it++)
        t[y8 + it * 8][x] = src[(size_t)(r0 + y8 + it * 8) * C + c0 + x];
    __syncthreads();
    #pragma unroll
    for (int it = 0; it < 4; it++) {
        int cc = y8 + it * 8;
        d[(size_t)(c0 + cc) * R + r0 + x] = __float2half(t[x][cc]);
    }
}

__global__ void conv_all(
    const float* __restrict__ x,  hf* xh, hf* xl,
    const float* __restrict__ wq, hf* qw,
    const float* __restrict__ wd, hf* dh, hf* dl,
    const float* __restrict__ wk, hf* kw,
    const float* __restrict__ wv, hf* vh, hf* vl,
    const float* __restrict__ wo, hf* ow)
{
    int t = blockIdx.x;
    if (t < 4096) {
        int i = t * 256 + threadIdx.x;
        float4 v = ((const float4*)x)[i];
        uint32_t h0, l0, h1, l1;
        split2h(v.x, v.y, h0, l0); split2h(v.z, v.w, h1, l1);
        ((uint2*)xh)[i] = make_uint2(h0, h1);
        ((uint2*)xl)[i] = make_uint2(l0, l1);
        return;
    }
    t -= 4096;
    if (t < 1024)      conv_T_s (wq, qw, DD, NQ, t & 31, t >> 5);
    else if (t < 1280) { t -= 1024; conv_T_hl(wd, dh, dl, DD, LD, t & 7, t >> 3); }
    else if (t < 1536) { t -= 1280; conv_T_s (wk, kw, LD, NQ, t & 31, t >> 5); }
    else if (t < 1792) { t -= 1536; conv_T_hl(wv, vh, vl, LD, NQ, t & 31, t >> 5); }
    else               { t -= 1792; conv_T_s (wo, ow, NQ, DD, t & 31, t >> 5); }
}

// ---------------- GEMM core (unchanged from R15) ----------------
#define GSTAGE 15360
#define GSM (3 * GSTAGE * 2)

template <int WMODE, int PASSES>
__device__ __forceinline__ void gemm_core(
    const hf* __restrict__ Ah, const hf* __restrict__ Al,
    const hf* __restrict__ Bh, const hf* __restrict__ Bl,
    float* __restrict__ C, hf* __restrict__ Ch, hf* __restrict__ Cl,
    int N, int K, int bm0, int bn0)
{
    extern __shared__ hf sm[];
    const int tid = threadIdx.x, lane = tid & 31, warp = tid >> 5;
    const int g = lane >> 2, tg = lane & 3;
    const int wm = warp >> 1, wn = warp & 1;

    float acc[2][4][4];
    #pragma unroll
    for (int mt = 0; mt < 2; mt++)
        #pragma unroll
        for (int nt = 0; nt < 4; nt++)
            #pragma unroll
            for (int r = 0; r < 4; r++) acc[mt][nt][r] = 0.0f;

    auto load_stage = [&](int s, int k0) {
        hf* As_h = sm + s * GSTAGE;
        hf* As_l = As_h + 5120;
        hf* Bs_h = As_h + 10240;
        hf* Bs_l = As_h + 12800;
        #pragma unroll
        for (int e = tid; e < 512; e += 256) {
            int r = e >> 2, c8 = (e & 3) * 8;
            cpa16(As_h + r*40 + c8, Ah + (size_t)(bm0+r)*K + k0 + c8);
            if (PASSES > 1)
                cpa16(As_l + r*40 + c8, Al + (size_t)(bm0+r)*K + k0 + c8);
        }
        {
            int r = tid >> 2, c8 = (tid & 3) * 8;
            cpa16(Bs_h + r*40 + c8, Bh + (size_t)(bn0+r)*K + k0 + c8);
            if (PASSES == 3)
                cpa16(Bs_l + r*40 + c8, Bl + (size_t)(bn0+r)*K + k0 + c8);
        }
        cpa_commit();
    };

    const int nkt = K / 32;
    load_stage(0, 0);
    if (nkt > 1) load_stage(1, 32);

    const int ar = (lane & 15), ac8 = (lane >> 4) << 3;
    const int br = (lane & 7) + ((lane & 16) ? 8 : 0);
    const int bc8 = (lane & 8);

    for (int kt = 0; kt < nkt; kt++) {
        if (kt + 1 < nkt) cpa_wait1(); else cpa_wait0();
        __syncthreads();
        if (kt + 2 < nkt) load_stage((kt + 2) % 3, (kt + 2) * 32);

        const hf* As_h = sm + (kt % 3) * GSTAGE;
        const hf* As_l = As_h + 5120;
        const hf* Bs_h = As_h + 10240;
        const hf* Bs_l = As_h + 12800;

        #pragma unroll
        for (int ks = 0; ks < 2; ks++) {
            const int ko = ks * 16;
            uint32_t ah[2][4], al[2][4];
            #pragma unroll
            for (int mt = 0; mt < 2; mt++) {
                ldsm4(ah[mt][0], ah[mt][1], ah[mt][2], ah[mt][3],
                      As_h + (wm*32 + mt*16 + ar)*40 + ko + ac8);
                if (PASSES > 1)
                    ldsm4(al[mt][0], al[mt][1], al[mt][2], al[mt][3],
                          As_l + (wm*32 + mt*16 + ar)*40 + ko + ac8);
            }
            #pragma unroll
            for (int np = 0; np < 2; np++) {
                uint32_t bh0, bh1, bh2, bh3;
                ldsm4(bh0, bh1, bh2, bh3, Bs_h + (wn*32 + np*16 + br)*40 + ko + bc8);
                uint32_t bl0 = 0, bl1 = 0, bl2 = 0, bl3 = 0;
                if (PASSES == 3)
                    ldsm4(bl0, bl1, bl2, bl3, Bs_l + (wn*32 + np*16 + br)*40 + ko + bc8);
                #pragma unroll
                for (int mt = 0; mt < 2; mt++) {
                    mmaf16(acc[mt][2*np],   ah[mt], bh0, bh1);
                    if (PASSES > 1)  mmaf16(acc[mt][2*np], al[mt], bh0, bh1);
                    if (PASSES == 3) mmaf16(acc[mt][2*np], ah[mt], bl0, bl1);
                    mmaf16(acc[mt][2*np+1], ah[mt], bh2, bh3);
                    if (PASSES > 1)  mmaf16(acc[mt][2*np+1], al[mt], bh2, bh3);
                    if (PASSES == 3) mmaf16(acc[mt][2*np+1], ah[mt], bl2, bl3);
                }
            }
        }
        __syncthreads();
    }

    #pragma unroll
    for (int mt = 0; mt < 2; mt++)
        #pragma unroll
        for (int nt = 0; nt < 4; nt++) {
            int r = bm0 + wm*32 + mt*16 + g;
            int c = bn0 + wn*32 + nt*8 + 2*tg;
            float* a = acc[mt][nt];
            if (WMODE == 0) {
                *(float2*)&C[(size_t)r*N + c]     = make_float2(a[0], a[1]);
                *(float2*)&C[(size_t)(r+8)*N + c] = make_float2(a[2], a[3]);
            } else if (WMODE == 1) {
                uint32_t h0, l0, h1, l1;
                split2h(a[0], a[1], h0, l0); split2h(a[2], a[3], h1, l1);
                *(uint32_t*)&Ch[(size_t)r*N + c]     = h0;
                *(uint32_t*)&Cl[(size_t)r*N + c]     = l0;
                *(uint32_t*)&Ch[(size_t)(r+8)*N + c] = h1;
                *(uint32_t*)&Cl[(size_t)(r+8)*N + c] = l1;
            } else if (WMODE == 2) {
                int b = r >> 11, l = r & 2047, hh = c >> 6, d = c & 63;
                size_t i0 = (((size_t)(b*16 + hh)) * 2048 + l) * 64 + d;
                *(__half2*)&Ch[i0]       = __floats2half2_rn(a[0], a[1]);
                *(__half2*)&Ch[i0 + 512] = __floats2half2_rn(a[2], a[3]);
            } else {
                int b = r >> 11, l = r & 2047, hh = c >> 6, d = c & 63;
                size_t i0 = (((size_t)(b*16 + hh)) * 64 + d) * 2048 + l;
                #pragma unroll
                for (int j = 0; j < 4; j++)
                    Ch[i0 + (size_t)(j & 1) * 2048 + (j >> 1) * 8] = __float2half(a[j]);
            }
        }
}

__global__ __launch_bounds__(256, 2) void gemm_qlat(
    const hf* __restrict__ xa_h, const hf* __restrict__ xa_l,
    const hf* __restrict__ wq,
    const hf* __restrict__ wd_h, const hf* __restrict__ wd_l,
    float* __restrict__ q, hf* __restrict__ la_h, hf* __restrict__ la_l)
{
    const int bx = blockIdx.x, bm0 = blockIdx.y * 128;
    if (bx < 16)
        gemm_core<0, 1>(xa_h, nullptr, wq, nullptr, q, nullptr, nullptr,
                        NQ, DD, bm0, bx * 64);
    else
        gemm_core<1, 3>(xa_h, xa_l, wd_h, wd_l, nullptr, la_h, la_l,
                        LD, DD, bm0, (bx - 16) * 64);
}

__global__ __launch_bounds__(256, 2) void gemm_kv(
    const hf* __restrict__ la_h, const hf* __restrict__ la_l,
    const hf* __restrict__ wk,
    const hf* __restrict__ wv_h, const hf* __restrict__ wv_l,
    hf* __restrict__ kf, hf* __restrict__ vtf)
{
    const int bx = blockIdx.x, bm0 = blockIdx.y * 128;
    if (bx < 16)
        gemm_core<2, 2>(la_h, la_l, wk, nullptr, nullptr, kf, nullptr,
                        NQ, LD, bm0, bx * 64);
    else
        gemm_core<3, 3>(la_h, la_l, wv_h, wv_l, nullptr, vtf, nullptr,
                        NQ, LD, bm0, (bx - 16) * 64);
}

__global__ __launch_bounds__(256, 2) void gemm_out(
    const hf* __restrict__ ya, const hf* __restrict__ wo,
    float* __restrict__ out)
{
    gemm_core<0, 1>(ya, nullptr, wo, nullptr, out, nullptr, nullptr,
                    DD, NQ, blockIdx.y * 128, blockIdx.x * 64);
}

// ---------------- Flash attention: split-K, additive partials --------------
// Fixed-max softmax => partial (o, l) over disjoint k-blocks combine by
// pure addition. Each q-tile handled by 2 CTAs (even/odd k-blocks).
#define ASTAGE 9216
#define AT_SMEM (2 * ASTAGE * 2)
__global__ __launch_bounds__(256, 2) void mla_attn(
    const float* __restrict__ q,
    const hf* __restrict__ kf, const hf* __restrict__ vtf,
    float* __restrict__ oacc, float* __restrict__ lacc)
{
    extern __shared__ hf smh[];
    const int bx = blockIdx.x;
    const int qbi = 15 - (bx >> 1);      // heavy tiles first
    const int sp  = bx & 1;              // split: even/odd k-blocks
    const int h = blockIdx.y, b = blockIdx.z;
    const int tid = threadIdx.x, lane = tid & 31, warp = tid >> 5;
    const int g = lane >> 2, tg = lane & 3;
    const int q0 = qbi * 128, wrow = warp * 16;
    const int bh = b * HH + h, rA = q0 + wrow + g;
    const float csc = 0.18033688f;

    const hf* kp0 = kf + (size_t)bh * LL * HD;
    const hf* vp0 = vtf + (size_t)bh * HD * LL;

    auto load_stage = [&](int s, int k0) {
        hf* ks = smh + s * ASTAGE;
        hf* vt = ks + 4608;
        #pragma unroll
        for (int e = tid; e < 512; e += 256) {
            int r = e >> 3, c8 = (e & 7) * 8;
            cpa16(ks + r*72 + c8, kp0 + (size_t)(k0 + r)*HD + c8);
            cpa16(vt + r*72 + c8, vp0 + (size_t)r*LL + k0 + c8);
        }
        cpa_commit();
    };

    load_stage(0, sp * 64);

    uint32_t q_[4][4];
    #pragma unroll
    for (int k = 0; k < 4; k++) {
        size_t base = (size_t)(b * LL + rA) * NQ + h * 64 + k * 16 + 2 * tg;
        float2 f00 = *(const float2*)&q[base];
        float2 f01 = *(const float2*)&q[base + 8];
        float2 f10 = *(const float2*)&q[base + (size_t)8 * NQ];
        float2 f11 = *(const float2*)&q[base + (size_t)8 * NQ + 8];
        __half2 h0 = __floats2half2_rn(f00.x * csc, f00.y * csc);
        __half2 h1 = __floats2half2_rn(f10.x * csc, f10.y * csc);
        __half2 h2 = __floats2half2_rn(f01.x * csc, f01.y * csc);
        __half2 h3 = __floats2half2_rn(f11.x * csc, f11.y * csc);
        q_[k][0] = *(uint32_t*)&h0; q_[k][1] = *(uint32_t*)&h1;
        q_[k][2] = *(uint32_t*)&h2; q_[k][3] = *(uint32_t*)&h3;
    }

    float o_[8][4];
    #pragma unroll
    for (int d = 0; d < 8; d++)
        #pragma unroll
        for (int r = 0; r < 4; r++) o_[d][r] = 0.0f;
    float l0 = 0.0f, l1 = 0.0f;

    const int nkb = 2 * qbi + 2;
    cpa_wait0();
    __syncthreads();

    const int br  = (lane & 7) + ((lane & 16) ? 8 : 0);
    const int bc8 = (lane & 8);

    for (int kb = sp, it = 0; kb < nkb; kb += 2, it++) {
        const int k0 = kb * 64;
        const int cur = it & 1;
        if (kb + 2 < nkb) load_stage(cur ^ 1, (kb + 2) * 64);

        if (!(k0 > q0 + wrow + 15)) {
            const hf* ks = smh + cur * ASTAGE;
            const hf* vt = ks + 4608;
            const bool diag = (k0 + 63 > q0 + wrow);

            #pragma unroll
            for (int np = 0; np < 4; np++) {
                const hf* krow = ks + (np*16 + br)*72 + bc8;

                float s0[4] = {0,0,0,0}, s1[4] = {0,0,0,0};
                uint32_t kfr[2][4];
                ldsm4(kfr[0][0], kfr[0][1], kfr[0][2], kfr[0][3], krow);
                #pragma unroll
                for (int k = 0; k < 4; k++) {
                    uint32_t* kc = kfr[k & 1];
                    if (k < 3) {
                        uint32_t* kn = kfr[(k + 1) & 1];
                        ldsm4(kn[0], kn[1], kn[2], kn[3], krow + (k+1)*16);
                    }
                    mmaf16(s0, q_[k], kc[0], kc[1]);
                    mmaf16(s1, q_[k], kc[2], kc[3]);
                }

                const int ko = np * 16;
                uint32_t vf[2][4];
                ldsm4(vf[0][0], vf[0][1], vf[0][2], vf[0][3],
                      vt + (0*16 + br)*72 + ko + bc8);

                if (diag) {
                    int cb0 = k0 + np*16 + 2*tg;
                    int cb1 = cb0 + 8;
                    if (cb0     > rA)     s0[0] = -1e30f;
                    if (cb0 + 1 > rA)     s0[1] = -1e30f;
                    if (cb0     > rA + 8) s0[2] = -1e30f;
                    if (cb0 + 1 > rA + 8) s0[3] = -1e30f;
                    if (cb1     > rA)     s1[0] = -1e30f;
                    if (cb1 + 1 > rA)     s1[1] = -1e30f;
                    if (cb1     > rA + 8) s1[2] = -1e30f;
                    if (cb1 + 1 > rA + 8) s1[3] = -1e30f;
                }

                s0[0] = ex2(s0[0]); s0[1] = ex2(s0[1]);
                s0[2] = ex2(s0[2]); s0[3] = ex2(s0[3]);
                s1[0] = ex2(s1[0]); s1[1] = ex2(s1[1]);
                s1[2] = ex2(s1[2]); s1[3] = ex2(s1[3]);
                l0 += s0[0] + s0[1] + s1[0] + s1[1];
                l1 += s0[2] + s0[3] + s1[2] + s1[3];

                uint32_t p_[4];
                __half2 p0 = __floats2half2_rn(s0[0], s0[1]);
                __half2 p1 = __floats2half2_rn(s0[2], s0[3]);
                __half2 p2 = __floats2half2_rn(s1[0], s1[1]);
                __half2 p3 = __floats2half2_rn(s1[2], s1[3]);
                p_[0] = *(uint32_t*)&p0; p_[1] = *(uint32_t*)&p1;
                p_[2] = *(uint32_t*)&p2; p_[3] = *(uint32_t*)&p3;

                #pragma unroll
                for (int dp = 0; dp < 4; dp++) {
                    uint32_t* vc = vf[dp & 1];
                    if (dp < 3) {
                        uint32_t* vn = vf[(dp + 1) & 1];
                        ldsm4(vn[0], vn[1], vn[2], vn[3],
                              vt + ((dp+1)*16 + br)*72 + ko + bc8);
                    }
                    mmaf16(o_[2*dp],   p_, vc[0], vc[1]);
                    mmaf16(o_[2*dp+1], p_, vc[2], vc[3]);
                }
            }
        }
        if (kb + 2 < nkb) cpa_wait0();
        __syncthreads();
    }

    // quad-reduce partial l; one lane per row adds to global
    l0 += __shfl_xor_sync(~0u, l0, 1, 4); l0 += __shfl_xor_sync(~0u, l0, 2, 4);
    l1 += __shfl_xor_sync(~0u, l1, 1, 4); l1 += __shfl_xor_sync(~0u, l1, 2, 4);
    if (tg == 0) {
        atomicAdd(&lacc[(size_t)(b * LL + rA) * HH + h], l0);
        atomicAdd(&lacc[(size_t)(b * LL + rA + 8) * HH + h], l1);
    }
    // accumulate partial o
    #pragma unroll
    for (int d = 0; d < 8; d++) {
        size_t oA = (size_t)(b * LL + rA) * NQ + h * 64 + d * 8 + 2 * tg;
        size_t oB = oA + (size_t)8 * NQ;
        atomicAdd(&oacc[oA],     o_[d][0]);
        atomicAdd(&oacc[oA + 1], o_[d][1]);
        atomicAdd(&oacc[oB],     o_[d][2]);
        atomicAdd(&oacc[oB + 1], o_[d][3]);
    }
}

// normalize: y = half(oacc / lacc[row,h])
__global__ void norm_y(const float* __restrict__ oacc,
                       const float* __restrict__ lacc, hf* __restrict__ y)
{
    int i = blockIdx.x * 256 + threadIdx.x;   // over BL*NQ/4
    float4 o = ((const float4*)oacc)[i];
    int base = i * 4;
    int row = base / NQ, hh = (base % NQ) >> 6;
    float inv = 1.0f / lacc[(size_t)row * HH + hh];
    __half2 y0 = __floats2half2_rn(o.x * inv, o.y * inv);
    __half2 y1 = __floats2half2_rn(o.z * inv, o.w * inv);
    ((uint2*)y)[i] = make_uint2(*(uint32_t*)&y0, *(uint32_t*)&y1);
}

extern "C" void kernel_launch(void* const* d_in, const int* in_sizes, int n_in,
                              void* d_out, int out_size)
{
    const float* x  = (const float*)d_in[0];
    const float* Wq = (const float*)d_in[1];
    const float* Wd = (const float*)d_in[2];
    const float* Wk = (const float*)d_in[3];
    const float* Wv = (const float*)d_in[4];
    const float* Wo = (const float*)d_in[5];
    float* out = (float*)d_out;

    float *pq, *poacc, *placc;
    cudaGetSymbolAddress((void**)&pq, g_q);
    cudaGetSymbolAddress((void**)&poacc, g_oacc);
    cudaGetSymbolAddress((void**)&placc, g_lacc);
    hf *xa_h,*xa_l,*la_h,*la_l,*ya;
    hf *wq,*wd_h,*wd_l,*wk,*wv_h,*wv_l,*wo;
    hf *kfp,*vtfp;
    cudaGetSymbolAddress((void**)&xa_h,g_xa_h); cudaGetSymbolAddress((void**)&xa_l,g_xa_l);
    cudaGetSymbolAddress((void**)&la_h,g_la_h); cudaGetSymbolAddress((void**)&la_l,g_la_l);
    cudaGetSymbolAddress((void**)&ya,g_ya);
    cudaGetSymbolAddress((void**)&wq,g_wq);
    cudaGetSymbolAddress((void**)&wd_h,g_wd_h); cudaGetSymbolAddress((void**)&wd_l,g_wd_l);
    cudaGetSymbolAddress((void**)&wk,g_wk);
    cudaGetSymbolAddress((void**)&wv_h,g_wv_h); cudaGetSymbolAddress((void**)&wv_l,g_wv_l);
    cudaGetSymbolAddress((void**)&wo,g_wo);
    cudaGetSymbolAddress((void**)&kfp,g_kf);   cudaGetSymbolAddress((void**)&vtfp,g_vtf);

    cudaFuncSetAttribute(gemm_qlat, cudaFuncAttributeMaxDynamicSharedMemorySize, GSM);
    cudaFuncSetAttribute(gemm_kv,   cudaFuncAttributeMaxDynamicSharedMemorySize, GSM);
    cudaFuncSetAttribute(gemm_out,  cudaFuncAttributeMaxDynamicSharedMemorySize, GSM);
    cudaFuncSetAttribute(mla_attn,  cudaFuncAttributeMaxDynamicSharedMemorySize, AT_SMEM);

    // zero accumulation buffers (overlaps with conv/gemm work)
    cudaMemsetAsync(poacc, 0, (size_t)BL * NQ * sizeof(float));
    cudaMemsetAsync(placc, 0, (size_t)BL * HH * sizeof(float));

    conv_all<<<6912, 256>>>(x, xa_h, xa_l, Wq, wq, Wd, wd_h, wd_l,
                            Wk, wk, Wv, wv_h, wv_l, Wo, wo);
    gemm_qlat<<<dim3(20, BL/128), 256, GSM>>>(xa_h, xa_l, wq,
                                              wd_h, wd_l, pq, la_h, la_l);
    gemm_kv<<<dim3(32, BL/128), 256, GSM>>>(la_h, la_l, wk,
                                            wv_h, wv_l, kfp, vtfp);
    mla_attn<<<dim3(32, HH, BB), 256, AT_SMEM>>>(pq, kfp, vtfp, poacc, placc);
    norm_y<<<BL*NQ/4/256, 256>>>(poacc, placc, ya);
    gemm_out<<<dim3(DD/64, BL/128), 256, GSM>>>(ya, wo, out);
}

// round 17
// speedup vs baseline: 1.0221x; 1.0221x over previous
#include <cuda_runtime.h>
#include <cuda_bf16.h>
#include <cuda_fp16.h>
#include <cstdint>

#define BB 2
#define LL 2048
#define DD 1024
#define HH 16
#define HD 64
#define LD 256
#define BL (BB*LL)
#define NQ (HH*HD)

typedef __half hf;

__device__ float g_q[BL*NQ];
__device__ float g_opart[2][BL*NQ];
__device__ float g_lpart[2][BL*HH];
__device__ hf g_xa_h[BL*DD], g_xa_l[BL*DD];
__device__ hf g_la_h[BL*LD], g_la_l[BL*LD];
__device__ hf g_ya[BL*NQ];
__device__ hf g_wq[NQ*DD];
__device__ hf g_wd_h[LD*DD], g_wd_l[LD*DD];
__device__ hf g_wk[NQ*LD];
__device__ hf g_wv_h[NQ*LD], g_wv_l[NQ*LD];
__device__ hf g_wo[DD*NQ];
__device__ hf g_kf[BB*HH*LL*HD];
__device__ hf g_vtf[BB*HH*HD*LL];

__device__ __forceinline__ void split2h(float x, float y, uint32_t& hi, uint32_t& lo) {
    __half2 h = __floats2half2_rn(x, y);
    float hx = __low2float(h), hy = __high2float(h);
    __half2 l = __floats2half2_rn(x - hx, y - hy);
    hi = *(uint32_t*)&h; lo = *(uint32_t*)&l;
}
__device__ __forceinline__ float ex2(float x) {
    float y; asm("ex2.approx.f32 %0, %1;" : "=f"(y) : "f"(x)); return y;
}
__device__ __forceinline__ void mmaf16(float* d, const uint32_t* a, uint32_t b0, uint32_t b1) {
    asm volatile("mma.sync.aligned.m16n8k16.row.col.f32.f16.f16.f32 "
        "{%0,%1,%2,%3}, {%4,%5,%6,%7}, {%8,%9}, {%0,%1,%2,%3};\n"
        : "+f"(d[0]), "+f"(d[1]), "+f"(d[2]), "+f"(d[3])
        : "r"(a[0]), "r"(a[1]), "r"(a[2]), "r"(a[3]), "r"(b0), "r"(b1));
}
__device__ __forceinline__ void ldsm4(uint32_t& r0, uint32_t& r1, uint32_t& r2, uint32_t& r3,
                                      const void* p) {
    uint32_t a = (uint32_t)__cvta_generic_to_shared(p);
    asm volatile("ldmatrix.sync.aligned.m8n8.x4.shared.b16 {%0,%1,%2,%3}, [%4];\n"
        : "=r"(r0), "=r"(r1), "=r"(r2), "=r"(r3) : "r"(a));
}
__device__ __forceinline__ void cpa16(void* dst, const void* src) {
    uint32_t a = (uint32_t)__cvta_generic_to_shared(dst);
    asm volatile("cp.async.cg.shared.global [%0], [%1], 16;\n" :: "r"(a), "l"(src));
}
__device__ __forceinline__ void cpa_commit() { asm volatile("cp.async.commit_group;\n"); }
__device__ __forceinline__ void cpa_wait0()  { asm volatile("cp.async.wait_group 0;\n"); }
__device__ __forceinline__ void cpa_wait1()  { asm volatile("cp.async.wait_group 1;\n"); }

// ---------------- fused conversions ----------------
__device__ __forceinline__ void conv_T_hl(
    const float* __restrict__ src, hf* __restrict__ dh, hf* __restrict__ dl,
    int R, int C, int cx, int rx)
{
    __shared__ float t[32][33];
    int x = threadIdx.x & 31, y8 = threadIdx.x >> 5;
    int c0 = cx * 32, r0 = rx * 32;
    #pragma unroll
    for (int it = 0; it < 4; it++)
        t[y8 + it * 8][x] = src[(size_t)(r0 + y8 + it * 8) * C + c0 + x];
    __syncthreads();
    #pragma unroll
    for (int it = 0; it < 4; it++) {
        int cc = y8 + it * 8;
        float v = t[x][cc];
        hf h = __float2half(v);
        dh[(size_t)(c0 + cc) * R + r0 + x] = h;
        dl[(size_t)(c0 + cc) * R + r0 + x] = __float2half(v - __half2float(h));
    }
}
__device__ __forceinline__ void conv_T_s(
    const float* __restrict__ src, hf* __restrict__ d,
    int R, int C, int cx, int rx)
{
    __shared__ float t[32][33];
    int x = threadIdx.x & 31, y8 = threadIdx.x >> 5;
    int c0 = cx * 32, r0 = rx * 32;
    #pragma unroll
    for (int it = 0; it < 4; it++)
        t[y8 + it * 8][x] = src[(size_t)(r0 + y8 + it * 8) * C + c0 + x];
    __syncthreads();
    #pragma unroll
    for (int it = 0; it < 4; it++) {
        int cc = y8 + it * 8;
        d[(size_t)(c0 + cc) * R + r0 + x] = __float2half(t[x][cc]);
    }
}

__global__ void conv_all(
    const float* __restrict__ x,  hf* xh, hf* xl,
    const float* __restrict__ wq, hf* qw,
    const float* __restrict__ wd, hf* dh, hf* dl,
    const float* __restrict__ wk, hf* kw,
    const float* __restrict__ wv, hf* vh, hf* vl,
    const float* __restrict__ wo, hf* ow)
{
    int t = blockIdx.x;
    if (t < 4096) {
        int i = t * 256 + threadIdx.x;
        float4 v = ((const float4*)x)[i];
        uint32_t h0, l0, h1, l1;
        split2h(v.x, v.y, h0, l0); split2h(v.z, v.w, h1, l1);
        ((uint2*)xh)[i] = make_uint2(h0, h1);
        ((uint2*)xl)[i] = make_uint2(l0, l1);
        return;
    }
    t -= 4096;
    if (t < 1024)      conv_T_s (wq, qw, DD, NQ, t & 31, t >> 5);
    else if (t < 1280) { t -= 1024; conv_T_hl(wd, dh, dl, DD, LD, t & 7, t >> 3); }
    else if (t < 1536) { t -= 1280; conv_T_s (wk, kw, LD, NQ, t & 31, t >> 5); }
    else if (t < 1792) { t -= 1536; conv_T_hl(wv, vh, vl, LD, NQ, t & 31, t >> 5); }
    else               { t -= 1792; conv_T_s (wo, ow, NQ, DD, t & 31, t >> 5); }
}

// ---------------- GEMM core (unchanged) ----------------
#define GSTAGE 15360
#define GSM (3 * GSTAGE * 2)

template <int WMODE, int PASSES>
__device__ __forceinline__ void gemm_core(
    const hf* __restrict__ Ah, const hf* __restrict__ Al,
    const hf* __restrict__ Bh, const hf* __restrict__ Bl,
    float* __restrict__ C, hf* __restrict__ Ch, hf* __restrict__ Cl,
    int N, int K, int bm0, int bn0)
{
    extern __shared__ hf sm[];
    const int tid = threadIdx.x, lane = tid & 31, warp = tid >> 5;
    const int g = lane >> 2, tg = lane & 3;
    const int wm = warp >> 1, wn = warp & 1;

    float acc[2][4][4];
    #pragma unroll
    for (int mt = 0; mt < 2; mt++)
        #pragma unroll
        for (int nt = 0; nt < 4; nt++)
            #pragma unroll
            for (int r = 0; r < 4; r++) acc[mt][nt][r] = 0.0f;

    auto load_stage = [&](int s, int k0) {
        hf* As_h = sm + s * GSTAGE;
        hf* As_l = As_h + 5120;
        hf* Bs_h = As_h + 10240;
        hf* Bs_l = As_h + 12800;
        #pragma unroll
        for (int e = tid; e < 512; e += 256) {
            int r = e >> 2, c8 = (e & 3) * 8;
            cpa16(As_h + r*40 + c8, Ah + (size_t)(bm0+r)*K + k0 + c8);
            if (PASSES > 1)
                cpa16(As_l + r*40 + c8, Al + (size_t)(bm0+r)*K + k0 + c8);
        }
        {
            int r = tid >> 2, c8 = (tid & 3) * 8;
            cpa16(Bs_h + r*40 + c8, Bh + (size_t)(bn0+r)*K + k0 + c8);
            if (PASSES == 3)
                cpa16(Bs_l + r*40 + c8, Bl + (size_t)(bn0+r)*K + k0 + c8);
        }
        cpa_commit();
    };

    const int nkt = K / 32;
    load_stage(0, 0);
    if (nkt > 1) load_stage(1, 32);

    const int ar = (lane & 15), ac8 = (lane >> 4) << 3;
    const int br = (lane & 7) + ((lane & 16) ? 8 : 0);
    const int bc8 = (lane & 8);

    for (int kt = 0; kt < nkt; kt++) {
        if (kt + 1 < nkt) cpa_wait1(); else cpa_wait0();
        __syncthreads();
        if (kt + 2 < nkt) load_stage((kt + 2) % 3, (kt + 2) * 32);

        const hf* As_h = sm + (kt % 3) * GSTAGE;
        const hf* As_l = As_h + 5120;
        const hf* Bs_h = As_h + 10240;
        const hf* Bs_l = As_h + 12800;

        #pragma unroll
        for (int ks = 0; ks < 2; ks++) {
            const int ko = ks * 16;
            uint32_t ah[2][4], al[2][4];
            #pragma unroll
            for (int mt = 0; mt < 2; mt++) {
                ldsm4(ah[mt][0], ah[mt][1], ah[mt][2], ah[mt][3],
                      As_h + (wm*32 + mt*16 + ar)*40 + ko + ac8);
                if (PASSES > 1)
                    ldsm4(al[mt][0], al[mt][1], al[mt][2], al[mt][3],
                          As_l + (wm*32 + mt*16 + ar)*40 + ko + ac8);
            }
            #pragma unroll
            for (int np = 0; np < 2; np++) {
                uint32_t bh0, bh1, bh2, bh3;
                ldsm4(bh0, bh1, bh2, bh3, Bs_h + (wn*32 + np*16 + br)*40 + ko + bc8);
                uint32_t bl0 = 0, bl1 = 0, bl2 = 0, bl3 = 0;
                if (PASSES == 3)
                    ldsm4(bl0, bl1, bl2, bl3, Bs_l + (wn*32 + np*16 + br)*40 + ko + bc8);
                #pragma unroll
                for (int mt = 0; mt < 2; mt++) {
                    mmaf16(acc[mt][2*np],   ah[mt], bh0, bh1);
                    if (PASSES > 1)  mmaf16(acc[mt][2*np], al[mt], bh0, bh1);
                    if (PASSES == 3) mmaf16(acc[mt][2*np], ah[mt], bl0, bl1);
                    mmaf16(acc[mt][2*np+1], ah[mt], bh2, bh3);
                    if (PASSES > 1)  mmaf16(acc[mt][2*np+1], al[mt], bh2, bh3);
                    if (PASSES == 3) mmaf16(acc[mt][2*np+1], ah[mt], bl2, bl3);
                }
            }
        }
        __syncthreads();
    }

    #pragma unroll
    for (int mt = 0; mt < 2; mt++)
        #pragma unroll
        for (int nt = 0; nt < 4; nt++) {
            int r = bm0 + wm*32 + mt*16 + g;
            int c = bn0 + wn*32 + nt*8 + 2*tg;
            float* a = acc[mt][nt];
            if (WMODE == 0) {
                *(float2*)&C[(size_t)r*N + c]     = make_float2(a[0], a[1]);
                *(float2*)&C[(size_t)(r+8)*N + c] = make_float2(a[2], a[3]);
            } else if (WMODE == 1) {
                uint32_t h0, l0, h1, l1;
                split2h(a[0], a[1], h0, l0); split2h(a[2], a[3], h1, l1);
                *(uint32_t*)&Ch[(size_t)r*N + c]     = h0;
                *(uint32_t*)&Cl[(size_t)r*N + c]     = l0;
                *(uint32_t*)&Ch[(size_t)(r+8)*N + c] = h1;
                *(uint32_t*)&Cl[(size_t)(r+8)*N + c] = l1;
            } else if (WMODE == 2) {
                int b = r >> 11, l = r & 2047, hh = c >> 6, d = c & 63;
                size_t i0 = (((size_t)(b*16 + hh)) * 2048 + l) * 64 + d;
                *(__half2*)&Ch[i0]       = __floats2half2_rn(a[0], a[1]);
                *(__half2*)&Ch[i0 + 512] = __floats2half2_rn(a[2], a[3]);
            } else {
                int b = r >> 11, l = r & 2047, hh = c >> 6, d = c & 63;
                size_t i0 = (((size_t)(b*16 + hh)) * 64 + d) * 2048 + l;
                #pragma unroll
                for (int j = 0; j < 4; j++)
                    Ch[i0 + (size_t)(j & 1) * 2048 + (j >> 1) * 8] = __float2half(a[j]);
            }
        }
}

__global__ __launch_bounds__(256, 2) void gemm_qlat(
    const hf* __restrict__ xa_h, const hf* __restrict__ xa_l,
    const hf* __restrict__ wq,
    const hf* __restrict__ wd_h, const hf* __restrict__ wd_l,
    float* __restrict__ q, hf* __restrict__ la_h, hf* __restrict__ la_l)
{
    const int bx = blockIdx.x, bm0 = blockIdx.y * 128;
    if (bx < 16)
        gemm_core<0, 1>(xa_h, nullptr, wq, nullptr, q, nullptr, nullptr,
                        NQ, DD, bm0, bx * 64);
    else
        gemm_core<1, 3>(xa_h, xa_l, wd_h, wd_l, nullptr, la_h, la_l,
                        LD, DD, bm0, (bx - 16) * 64);
}

__global__ __launch_bounds__(256, 2) void gemm_kv(
    const hf* __restrict__ la_h, const hf* __restrict__ la_l,
    const hf* __restrict__ wk,
    const hf* __restrict__ wv_h, const hf* __restrict__ wv_l,
    hf* __restrict__ kf, hf* __restrict__ vtf)
{
    const int bx = blockIdx.x, bm0 = blockIdx.y * 128;
    if (bx < 16)
        gemm_core<2, 2>(la_h, la_l, wk, nullptr, nullptr, kf, nullptr,
                        NQ, LD, bm0, bx * 64);
    else
        gemm_core<3, 3>(la_h, la_l, wv_h, wv_l, nullptr, vtf, nullptr,
                        NQ, LD, bm0, (bx - 16) * 64);
}

__global__ __launch_bounds__(256, 2) void gemm_out(
    const hf* __restrict__ ya, const hf* __restrict__ wo,
    float* __restrict__ out)
{
    gemm_core<0, 1>(ya, nullptr, wo, nullptr, out, nullptr, nullptr,
                    DD, NQ, blockIdx.y * 128, blockIdx.x * 64);
}

// ---------------- Flash attention: split-K, per-split buffers (no atomics) --
#define ASTAGE 9216
#define AT_SMEM (2 * ASTAGE * 2)
__global__ __launch_bounds__(256, 2) void mla_attn(
    const float* __restrict__ q,
    const hf* __restrict__ kf, const hf* __restrict__ vtf,
    float* __restrict__ opart, float* __restrict__ lpart)
{
    extern __shared__ hf smh[];
    const int bx = blockIdx.x;
    const int qbi = 15 - (bx >> 1);      // heavy tiles first
    const int sp  = bx & 1;              // split: even/odd k-blocks
    const int h = blockIdx.y, b = blockIdx.z;
    const int tid = threadIdx.x, lane = tid & 31, warp = tid >> 5;
    const int g = lane >> 2, tg = lane & 3;
    const int q0 = qbi * 128, wrow = warp * 16;
    const int bh = b * HH + h, rA = q0 + wrow + g;
    const float csc = 0.18033688f;

    float* od = opart + (size_t)sp * BL * NQ;
    float* ld = lpart + (size_t)sp * BL * HH;

    const hf* kp0 = kf + (size_t)bh * LL * HD;
    const hf* vp0 = vtf + (size_t)bh * HD * LL;

    auto load_stage = [&](int s, int k0) {
        hf* ks = smh + s * ASTAGE;
        hf* vt = ks + 4608;
        #pragma unroll
        for (int e = tid; e < 512; e += 256) {
            int r = e >> 3, c8 = (e & 7) * 8;
            cpa16(ks + r*72 + c8, kp0 + (size_t)(k0 + r)*HD + c8);
            cpa16(vt + r*72 + c8, vp0 + (size_t)r*LL + k0 + c8);
        }
        cpa_commit();
    };

    load_stage(0, sp * 64);

    uint32_t q_[4][4];
    #pragma unroll
    for (int k = 0; k < 4; k++) {
        size_t base = (size_t)(b * LL + rA) * NQ + h * 64 + k * 16 + 2 * tg;
        float2 f00 = *(const float2*)&q[base];
        float2 f01 = *(const float2*)&q[base + 8];
        float2 f10 = *(const float2*)&q[base + (size_t)8 * NQ];
        float2 f11 = *(const float2*)&q[base + (size_t)8 * NQ + 8];
        __half2 h0 = __floats2half2_rn(f00.x * csc, f00.y * csc);
        __half2 h1 = __floats2half2_rn(f10.x * csc, f10.y * csc);
        __half2 h2 = __floats2half2_rn(f01.x * csc, f01.y * csc);
        __half2 h3 = __floats2half2_rn(f11.x * csc, f11.y * csc);
        q_[k][0] = *(uint32_t*)&h0; q_[k][1] = *(uint32_t*)&h1;
        q_[k][2] = *(uint32_t*)&h2; q_[k][3] = *(uint32_t*)&h3;
    }

    float o_[8][4];
    #pragma unroll
    for (int d = 0; d < 8; d++)
        #pragma unroll
        for (int r = 0; r < 4; r++) o_[d][r] = 0.0f;
    float l0 = 0.0f, l1 = 0.0f;

    const int nkb = 2 * qbi + 2;
    cpa_wait0();
    __syncthreads();

    const int br  = (lane & 7) + ((lane & 16) ? 8 : 0);
    const int bc8 = (lane & 8);

    for (int kb = sp, it = 0; kb < nkb; kb += 2, it++) {
        const int k0 = kb * 64;
        const int cur = it & 1;
        if (kb + 2 < nkb) load_stage(cur ^ 1, (kb + 2) * 64);

        if (!(k0 > q0 + wrow + 15)) {
            const hf* ks = smh + cur * ASTAGE;
            const hf* vt = ks + 4608;
            const bool diag = (k0 + 63 > q0 + wrow);

            #pragma unroll
            for (int np = 0; np < 4; np++) {
                const hf* krow = ks + (np*16 + br)*72 + bc8;

                float s0[4] = {0,0,0,0}, s1[4] = {0,0,0,0};
                uint32_t kfr[2][4];
                ldsm4(kfr[0][0], kfr[0][1], kfr[0][2], kfr[0][3], krow);
                #pragma unroll
                for (int k = 0; k < 4; k++) {
                    uint32_t* kc = kfr[k & 1];
                    if (k < 3) {
                        uint32_t* kn = kfr[(k + 1) & 1];
                        ldsm4(kn[0], kn[1], kn[2], kn[3], krow + (k+1)*16);
                    }
                    mmaf16(s0, q_[k], kc[0], kc[1]);
                    mmaf16(s1, q_[k], kc[2], kc[3]);
                }

                const int ko = np * 16;
                uint32_t vf[2][4];
                ldsm4(vf[0][0], vf[0][1], vf[0][2], vf[0][3],
                      vt + (0*16 + br)*72 + ko + bc8);

                if (diag) {
                    int cb0 = k0 + np*16 + 2*tg;
                    int cb1 = cb0 + 8;
                    if (cb0     > rA)     s0[0] = -1e30f;
                    if (cb0 + 1 > rA)     s0[1] = -1e30f;
                    if (cb0     > rA + 8) s0[2] = -1e30f;
                    if (cb0 + 1 > rA + 8) s0[3] = -1e30f;
                    if (cb1     > rA)     s1[0] = -1e30f;
                    if (cb1 + 1 > rA)     s1[1] = -1e30f;
                    if (cb1     > rA + 8) s1[2] = -1e30f;
                    if (cb1 + 1 > rA + 8) s1[3] = -1e30f;
                }

                s0[0] = ex2(s0[0]); s0[1] = ex2(s0[1]);
                s0[2] = ex2(s0[2]); s0[3] = ex2(s0[3]);
                s1[0] = ex2(s1[0]); s1[1] = ex2(s1[1]);
                s1[2] = ex2(s1[2]); s1[3] = ex2(s1[3]);
                l0 += s0[0] + s0[1] + s1[0] + s1[1];
                l1 += s0[2] + s0[3] + s1[2] + s1[3];

                uint32_t p_[4];
                __half2 p0 = __floats2half2_rn(s0[0], s0[1]);
                __half2 p1 = __floats2half2_rn(s0[2], s0[3]);
                __half2 p2 = __floats2half2_rn(s1[0], s1[1]);
                __half2 p3 = __floats2half2_rn(s1[2], s1[3]);
                p_[0] = *(uint32_t*)&p0; p_[1] = *(uint32_t*)&p1;
                p_[2] = *(uint32_t*)&p2; p_[3] = *(uint32_t*)&p3;

                #pragma unroll
                for (int dp = 0; dp < 4; dp++) {
                    uint32_t* vc = vf[dp & 1];
                    if (dp < 3) {
                        uint32_t* vn = vf[(dp + 1) & 1];
                        ldsm4(vn[0], vn[1], vn[2], vn[3],
                              vt + ((dp+1)*16 + br)*72 + ko + bc8);
                    }
                    mmaf16(o_[2*dp],   p_, vc[0], vc[1]);
                    mmaf16(o_[2*dp+1], p_, vc[2], vc[3]);
                }
            }
        }
        if (kb + 2 < nkb) cpa_wait0();
        __syncthreads();
    }

    // quad-reduce partial l; plain stores to split-private buffers
    l0 += __shfl_xor_sync(~0u, l0, 1, 4); l0 += __shfl_xor_sync(~0u, l0, 2, 4);
    l1 += __shfl_xor_sync(~0u, l1, 1, 4); l1 += __shfl_xor_sync(~0u, l1, 2, 4);
    if (tg == 0) {
        ld[(size_t)(b * LL + rA) * HH + h] = l0;
        ld[(size_t)(b * LL + rA + 8) * HH + h] = l1;
    }
    #pragma unroll
    for (int d = 0; d < 8; d++) {
        size_t oA = (size_t)(b * LL + rA) * NQ + h * 64 + d * 8 + 2 * tg;
        size_t oB = oA + (size_t)8 * NQ;
        *(float2*)&od[oA] = make_float2(o_[d][0], o_[d][1]);
        *(float2*)&od[oB] = make_float2(o_[d][2], o_[d][3]);
    }
}

// normalize: y = half((o0+o1) / (l0+l1))
__global__ void norm_y(const float* __restrict__ opart,
                       const float* __restrict__ lpart, hf* __restrict__ y)
{
    int i = blockIdx.x * 256 + threadIdx.x;   // over BL*NQ/4
    float4 o0 = ((const float4*)opart)[i];
    float4 o1 = ((const float4*)(opart + (size_t)BL * NQ))[i];
    int base = i * 4;
    int row = base / NQ, hh = (base % NQ) >> 6;
    size_t li = (size_t)row * HH + hh;
    float inv = 1.0f / (lpart[li] + lpart[li + (size_t)BL * HH]);
    __half2 y0 = __floats2half2_rn((o0.x + o1.x) * inv, (o0.y + o1.y) * inv);
    __half2 y1 = __floats2half2_rn((o0.z + o1.z) * inv, (o0.w + o1.w) * inv);
    ((uint2*)y)[i] = make_uint2(*(uint32_t*)&y0, *(uint32_t*)&y1);
}

extern "C" void kernel_launch(void* const* d_in, const int* in_sizes, int n_in,
                              void* d_out, int out_size)
{
    const float* x  = (const float*)d_in[0];
    const float* Wq = (const float*)d_in[1];
    const float* Wd = (const float*)d_in[2];
    const float* Wk = (const float*)d_in[3];
    const float* Wv = (const float*)d_in[4];
    const float* Wo = (const float*)d_in[5];
    float* out = (float*)d_out;

    float *pq, *popart, *plpart;
    cudaGetSymbolAddress((void**)&pq, g_q);
    cudaGetSymbolAddress((void**)&popart, g_opart);
    cudaGetSymbolAddress((void**)&plpart, g_lpart);
    hf *xa_h,*xa_l,*la_h,*la_l,*ya;
    hf *wq,*wd_h,*wd_l,*wk,*wv_h,*wv_l,*wo;
    hf *kfp,*vtfp;
    cudaGetSymbolAddress((void**)&xa_h,g_xa_h); cudaGetSymbolAddress((void**)&xa_l,g_xa_l);
    cudaGetSymbolAddress((void**)&la_h,g_la_h); cudaGetSymbolAddress((void**)&la_l,g_la_l);
    cudaGetSymbolAddress((void**)&ya,g_ya);
    cudaGetSymbolAddress((void**)&wq,g_wq);
    cudaGetSymbolAddress((void**)&wd_h,g_wd_h); cudaGetSymbolAddress((void**)&wd_l,g_wd_l);
    cudaGetSymbolAddress((void**)&wk,g_wk);
    cudaGetSymbolAddress((void**)&wv_h,g_wv_h); cudaGetSymbolAddress((void**)&wv_l,g_wv_l);
    cudaGetSymbolAddress((void**)&wo,g_wo);
    cudaGetSymbolAddress((void**)&kfp,g_kf);   cudaGetSymbolAddress((void**)&vtfp,g_vtf);

    cudaFuncSetAttribute(gemm_qlat, cudaFuncAttributeMaxDynamicSharedMemorySize, GSM);
    cudaFuncSetAttribute(gemm_kv,   cudaFuncAttributeMaxDynamicSharedMemorySize, GSM);
    cudaFuncSetAttribute(gemm_out,  cudaFuncAttributeMaxDynamicSharedMemorySize, GSM);
    cudaFuncSetAttribute(mla_attn,  cudaFuncAttributeMaxDynamicSharedMemorySize, AT_SMEM);

    conv_all<<<6912, 256>>>(x, xa_h, xa_l, Wq, wq, Wd, wd_h, wd_l,
                            Wk, wk, Wv, wv_h, wv_l, Wo, wo);
    gemm_qlat<<<dim3(20, BL/128), 256, GSM>>>(xa_h, xa_l, wq,
                                              wd_h, wd_l, pq, la_h, la_l);
    gemm_kv<<<dim3(32, BL/128), 256, GSM>>>(la_h, la_l, wk,
                                            wv_h, wv_l, kfp, vtfp);
    mla_attn<<<dim3(32, HH, BB), 256, AT_SMEM>>>(pq, kfp, vtfp, popart, plpart);
    norm_y<<<BL*NQ/4/256, 256>>>(popart, plpart, ya);
    gemm_out<<<dim3(DD/64, BL/128), 256, GSM>>>(ya, wo, out);
}